// round 5
// baseline (speedup 1.0000x reference)
#include <cuda_runtime.h>
#include <climits>

// Fixed problem shape: B=8, C=1, H=W=768.
#define BB    8
#define HH    768
#define WW    768
#define HWSZ  (HH * WW)          // 589824
#define NTOT  (BB * HWSZ)        // 4718592
#define N4    (NTOT / 4)

#define TS        32
#define TILES_X   24
#define TILES_Y   24
#define NTILES    (BB * TILES_X * TILES_Y)   // 4608

#define EPT   (23 * 768)         // per-image boundary edges, one orientation
#define EPI   (2 * EPT)
#define NEDGE (BB * EPI)         // 282624

#define AGG_BLOCKS  2048
#define ROOT_BLOCKS 1024

#define SCALEF 16777216.0f       // 2^24 fixed point for deterministic err sums

// Scratch (static __device__ arrays; allocation-free kernel_launch).
__device__ int      g_parp[NTOT];          // pred UF parents (tile-root entries only)
__device__ int      g_part[NTOT];          // target UF parents (tile-root entries only)
__device__ int2     g_mm[NTOT];            // {min,max} target root per pred root
__device__ unsigned long long g_S[NTOT];   // per pred tile-root: fixed-point sum of pl over fg&~tg pixels
__device__ int      g_edge[2][NTILES * 4 * 32];  // tile edge roots: [mask][tile][edge][pos]
__device__ int2     g_wl[NTOT];            // overlap pairs (predRootGi, targRootGi)
__device__ int      g_rl[NTOT / 2];        // pred tile-root list (max 512/tile, 4-conn)
__device__ int      g_nwl, g_nrl;          // worklist counters (zero-init; reset in k_root)
__device__ int      g_flag, g_neg, g_ctrf; // rescale flag machinery (self-resetting)
__device__ int      g_ctr;                 // k_root last-block counter
__device__ double   g_psum[NTILES];
__device__ unsigned long long g_esum[ROOT_BLOCKS];

// Exact reference arithmetic for (x + 1.0) * 0.5 without FMA contraction.
__device__ __forceinline__ float resc01(float x) {
    return __fmul_rn(__fadd_rn(x, 1.0f), 0.5f);
}

// ---------------------------------------------------------------------------
// Union-find (min-index rooting; parent <= child invariant)
// ---------------------------------------------------------------------------
__device__ __forceinline__ int uf_find(const int* L, int x) {
    int p = L[x];
    while (p != x) { x = p; p = L[x]; }
    return x;
}

__device__ __forceinline__ int uf_findc(int* L, int x) {   // find + compress
    int r = x, p = L[r];
    while (p != r) { r = p; p = L[r]; }
    while (L[x] != r) { int nx = L[x]; L[x] = r; x = nx; }
    return r;
}

__device__ __forceinline__ void uf_union(int* L, int a, int b) {
    int ra = uf_find(L, a);
    int rb = uf_find(L, b);
    while (ra != rb) {
        int hi = ra > rb ? ra : rb;
        int lo = ra > rb ? rb : ra;
        int old = atomicMin(&L[hi], lo);
        if (old == hi) break;
        ra = lo;
        rb = old;
    }
}

// Shared-memory union-find.
__device__ __forceinline__ int s_find(const int* L, int x) {
    int p = L[x];
    while (p != x) { x = p; p = L[x]; }
    return x;
}

__device__ __forceinline__ void s_union(int* L, int a, int b) {
    int ra = s_find(L, a);
    int rb = s_find(L, b);
    while (ra != rb) {
        int hi = ra > rb ? ra : rb;
        int lo = ra > rb ? rb : ra;
        int old = atomicMin(&L[hi], lo);
        if (old == hi) break;
        ra = lo;
        rb = old;
    }
}

// ---------------------------------------------------------------------------
// Kernels
// ---------------------------------------------------------------------------
// Publish the rescale flag fresh each run (last-block pattern; self-resetting).
__global__ void k_flag(const float4* __restrict__ pred) {
    int i = blockIdx.x * blockDim.x + threadIdx.x;
    float4 v = pred[i];
    bool neg = (v.x < 0.f) | (v.y < 0.f) | (v.z < 0.f) | (v.w < 0.f);
    bool bneg = __syncthreads_or(neg);
    __shared__ bool last;
    if (threadIdx.x == 0) {
        if (bneg) atomicOr(&g_neg, 1);
        __threadfence();
        last = (atomicAdd(&g_ctrf, 1) == (int)gridDim.x - 1);
    }
    __syncthreads();
    if (last && threadIdx.x == 0) { g_flag = g_neg; g_neg = 0; g_ctrf = 0; }
}

// Per 32x32 tile: masks, in-tile CCL, per-component fixed-point loss sums,
// base-sum block reduction, edge-root export, and worklist emission.
__global__ void k_tile(const float* __restrict__ pred,
                       const float* __restrict__ target) {
    __shared__ int lp[TS * TS];
    __shared__ int lt[TS * TS];
    __shared__ unsigned long long sS[TS * TS];
    __shared__ double shd[TS * TS];
    __shared__ int s_wcnt, s_rcnt, s_wbase, s_rbase;

    int lx = threadIdx.x, ly = threadIdx.y;
    int l  = ly * TS + lx;
    int txi = blockIdx.x, tyi = blockIdx.y, b = blockIdx.z;
    int gx = txi * TS + lx;
    int gy = tyi * TS + ly;
    int gi = b * HWSZ + gy * WW + gx;
    int tidx = (b * TILES_Y + tyi) * TILES_X + txi;

    bool  resc = (g_flag != 0);
    float p = pred[gi];
    float t = target[gi];
    float pp  = resc ? resc01(p) : p;
    float t01 = resc01(t);
    bool mp = pp  > 0.5f;
    bool mt = t01 > 0.5f;
    float pl = fabsf(pp - t01);

    lp[l] = mp ? l : -1;
    lt[l] = mt ? l : -1;
    sS[l] = 0ull;
    if (l == 0) { s_wcnt = 0; s_rcnt = 0; }
    __syncthreads();

    if (mp) {
        if (lx > 0 && lp[l - 1]  >= 0) s_union(lp, l, l - 1);
        if (ly > 0 && lp[l - TS] >= 0) s_union(lp, l, l - TS);
    }
    if (mt) {
        if (lx > 0 && lt[l - 1]  >= 0) s_union(lt, l, l - 1);
        if (ly > 0 && lt[l - TS] >= 0) s_union(lt, l, l - TS);
    }
    __syncthreads();

    int rp = mp ? s_find(lp, l) : -1;
    int rt = mt ? s_find(lt, l) : -1;
    if (mp && !mt)
        atomicAdd(&sS[rp], __float2ull_rn(pl * SCALEF));   // integer: order-invariant
    __syncthreads();

    int rpg = -1, rtg = -1;
    if (rp >= 0) rpg = b * HWSZ + (tyi * TS + (rp >> 5)) * WW + txi * TS + (rp & 31);
    if (rt >= 0) rtg = b * HWSZ + (tyi * TS + (rt >> 5)) * WW + txi * TS + (rt & 31);

    int wpos = -1, rpos = -1;
    if (mp && rp == l) {            // pred tile-root pixel
        g_parp[gi] = gi;
        g_mm[gi]   = make_int2(INT_MAX, -1);
        g_S[gi]    = sS[l];
        rpos = atomicAdd(&s_rcnt, 1);
    }
    if (mt && rt == l) g_part[gi] = gi;
    if (mp && mt) wpos = atomicAdd(&s_wcnt, 1);

    // Edge-root export (0=top,1=bottom,2=left,3=right).
    if (ly == 0)      { g_edge[0][(tidx*4+0)*32+lx] = rpg; g_edge[1][(tidx*4+0)*32+lx] = rtg; }
    if (ly == TS - 1) { g_edge[0][(tidx*4+1)*32+lx] = rpg; g_edge[1][(tidx*4+1)*32+lx] = rtg; }
    if (lx == 0)      { g_edge[0][(tidx*4+2)*32+ly] = rpg; g_edge[1][(tidx*4+2)*32+ly] = rtg; }
    if (lx == TS - 1) { g_edge[0][(tidx*4+3)*32+ly] = rpg; g_edge[1][(tidx*4+3)*32+ly] = rtg; }

    __syncthreads();
    if (l == 0) {
        s_wbase = s_wcnt ? atomicAdd(&g_nwl, s_wcnt) : 0;
        s_rbase = s_rcnt ? atomicAdd(&g_nrl, s_rcnt) : 0;
    }
    __syncthreads();
    if (wpos >= 0) g_wl[s_wbase + wpos] = make_int2(rpg, rtg);
    if (rpos >= 0) g_rl[s_rbase + rpos] = gi;

    // Deterministic base-sum block reduction.
    shd[l] = (double)pl;
    __syncthreads();
    for (int off = (TS * TS) / 2; off > 0; off >>= 1) {
        if (l < off) shd[l] += shd[l + off];
        __syncthreads();
    }
    if (l == 0) g_psum[tidx] = shd[0];
}

// Merge across tile boundaries using exported edge roots (both masks).
__global__ void k_bmerge() {
    int tid = blockIdx.x * blockDim.x + threadIdx.x;
    if (tid >= NEDGE) return;
    int b = tid / EPI;
    int e = tid % EPI;
    int aIdx, cIdx;
    if (e < EPT) {                              // vertical boundary
        int bi = e / HH, y = e % HH;
        int tyi = y >> 5, pos = y & 31;
        int tl = (b * TILES_Y + tyi) * TILES_X + bi;     // left tile
        aIdx = (tl * 4 + 3) * 32 + pos;                  // its right column
        cIdx = ((tl + 1) * 4 + 2) * 32 + pos;            // right tile's left column
    } else {                                    // horizontal boundary
        e -= EPT;
        int bi = e / WW, x = e % WW;
        int txi = x >> 5, pos = x & 31;
        int tt = (b * TILES_Y + bi) * TILES_X + txi;     // top tile
        aIdx = (tt * 4 + 1) * 32 + pos;                  // its bottom row
        cIdx = ((tt + TILES_X) * 4 + 0) * 32 + pos;      // bottom tile's top row
    }
    int a = g_edge[0][aIdx], c = g_edge[0][cIdx];
    if (a >= 0 && c >= 0) uf_union(g_parp, a, c);
    a = g_edge[1][aIdx]; c = g_edge[1][cIdx];
    if (a >= 0 && c >= 0) uf_union(g_part, a, c);
}

// Aggregate target-root min/max per pred root over the overlap worklist.
__global__ void k_agg() {
    int n = g_nwl;
    for (int i = blockIdx.x * blockDim.x + threadIdx.x; i < n;
         i += gridDim.x * blockDim.x) {
        int2 pr = g_wl[i];
        int rp = uf_findc(g_parp, pr.x);
        int rt = uf_findc(g_part, pr.y);
        atomicMin(&g_mm[rp].x, rt);
        atomicMax(&g_mm[rp].y, rt);
    }
}

// Per pred tile-root: merged? then 10*S. Fused deterministic final reduction.
__global__ void k_root(float* __restrict__ out) {
    __shared__ double shd[256];
    __shared__ unsigned long long shu[256];
    int n = g_nrl;
    unsigned long long es = 0;
    for (int i = blockIdx.x * blockDim.x + threadIdx.x; i < n;
         i += gridDim.x * blockDim.x) {
        int r = g_rl[i];
        int R = uf_find(g_parp, r);
        int2 mm = g_mm[R];
        if (mm.y > mm.x) es += g_S[r];
    }
    shu[threadIdx.x] = es;
    __syncthreads();
    for (int off = 128; off > 0; off >>= 1) {
        if (threadIdx.x < off) shu[threadIdx.x] += shu[threadIdx.x + off];
        __syncthreads();
    }
    __shared__ bool last;
    if (threadIdx.x == 0) {
        g_esum[blockIdx.x] = shu[0];
        __threadfence();
        last = (atomicAdd(&g_ctr, 1) == (int)gridDim.x - 1);
    }
    __syncthreads();
    if (last) {
        double bs = 0.0;
        for (int k = threadIdx.x; k < NTILES; k += 256) bs += g_psum[k];
        unsigned long long eu = 0;
        for (int k = threadIdx.x; k < ROOT_BLOCKS; k += 256) eu += g_esum[k];
        shd[threadIdx.x] = bs;
        shu[threadIdx.x] = eu;
        __syncthreads();
        for (int off = 128; off > 0; off >>= 1) {
            if (threadIdx.x < off) {
                shd[threadIdx.x] += shd[threadIdx.x + off];
                shu[threadIdx.x] += shu[threadIdx.x + off];
            }
            __syncthreads();
        }
        if (threadIdx.x == 0) {
            double total = shd[0] + 10.0 * ((double)shu[0] / (double)SCALEF);
            out[0] = (float)(total / (double)NTOT);
            g_ctr = 0; g_nwl = 0; g_nrl = 0;   // reset for next replay
        }
    }
}

// ---------------------------------------------------------------------------
extern "C" void kernel_launch(void* const* d_in, const int* in_sizes, int n_in,
                              void* d_out, int out_size) {
    const float* pred   = (const float*)d_in[0];
    const float* target = (const float*)d_in[1];
    float* out = (float*)d_out;

    k_flag<<<N4 / 256, 256>>>((const float4*)pred);
    k_tile<<<dim3(TILES_X, TILES_Y, BB), dim3(TS, TS)>>>(pred, target);
    k_bmerge<<<(NEDGE + 255) / 256, 256>>>();
    k_agg<<<AGG_BLOCKS, 256>>>();
    k_root<<<ROOT_BLOCKS, 256>>>(out);
}

// round 6
// speedup vs baseline: 1.2652x; 1.2652x over previous
#include <cuda_runtime.h>
#include <climits>

// Fixed problem shape: B=8, C=1, H=W=768.
#define BB    8
#define HH    768
#define WW    768
#define HWSZ  (HH * WW)          // 589824
#define NTOT  (BB * HWSZ)        // 4718592
#define N4    (NTOT / 4)         // 1179648

#define TS        32
#define TILES_X   24
#define TILES_Y   24

#define EPT   (23 * 768)         // per-image boundary edges, one orientation
#define EPI   (2 * EPT)          // 35328
#define NEDGE (2 * BB * EPI)     // 565248 (thread = one edge of one mask)

#define LOSS_BLOCKS (N4 / 256)   // 4608, exact cover

// Scratch (static __device__ arrays; allocation-free kernel_launch).
__device__ int    g_labp[NTOT];   // pred labels / UF parents (-1 = bg)
__device__ int    g_labt[NTOT];   // target labels / UF parents
__device__ int2   g_mm[NTOT];     // {min,max} target root per pred root (root idx only)
__device__ int    g_flag;         // rescale flag (published fresh by k_flag)
__device__ int    g_neg, g_ctrf;  // k_flag reduction state (zero-init, self-reset)
__device__ int    g_ctr;          // k_loss last-block counter (zero-init, self-reset)
__device__ double g_psum[LOSS_BLOCKS];

// Exact reference arithmetic for (x + 1.0) * 0.5 without FMA contraction.
__device__ __forceinline__ float resc01(float x) {
    return __fmul_rn(__fadd_rn(x, 1.0f), 0.5f);
}

// ---------------------------------------------------------------------------
// Union-find (min-index rooting; parent <= child invariant)
// ---------------------------------------------------------------------------
__device__ __forceinline__ int uf_find(const int* L, int x) {
    int p = L[x];
    while (p != x) { x = p; p = L[x]; }
    return x;
}

// Find + full path compression (races only shorten paths -> benign).
__device__ __forceinline__ int uf_findc(int* L, int x) {
    int r = x, p = L[r];
    while (p != r) { r = p; p = L[r]; }
    while (L[x] != r) { int nx = L[x]; L[x] = r; x = nx; }
    return r;
}

__device__ __forceinline__ void uf_union(int* L, int a, int b) {
    int ra = uf_find(L, a);
    int rb = uf_find(L, b);
    while (ra != rb) {
        int hi = ra > rb ? ra : rb;
        int lo = ra > rb ? rb : ra;
        int old = atomicMin(&L[hi], lo);
        if (old == hi) break;
        ra = lo;
        rb = old;
    }
}

// Shared-memory union-find.
__device__ __forceinline__ int s_find(const int* L, int x) {
    int p = L[x];
    while (p != x) { x = p; p = L[x]; }
    return x;
}

__device__ __forceinline__ void s_union(int* L, int a, int b) {
    int ra = s_find(L, a);
    int rb = s_find(L, b);
    while (ra != rb) {
        int hi = ra > rb ? ra : rb;
        int lo = ra > rb ? rb : ra;
        int old = atomicMin(&L[hi], lo);
        if (old == hi) break;
        ra = lo;
        rb = old;
    }
}

// Warp-deduplicated find: one lane per distinct label value chases, broadcasts.
__device__ __forceinline__ int warp_findc(int* L, int lab) {
    unsigned grp = __match_any_sync(0xffffffffu, lab);
    int leader = __ffs(grp) - 1;
    int lane = threadIdx.x & 31;
    int r = -1;
    if (lane == leader && lab >= 0) r = uf_findc(L, lab);
    return __shfl_sync(0xffffffffu, r, leader);
}

// ---------------------------------------------------------------------------
// Kernels
// ---------------------------------------------------------------------------
// Publish the rescale flag fresh each run (last-block pattern; self-resetting).
__global__ void k_flag(const float4* __restrict__ pred) {
    int i = blockIdx.x * blockDim.x + threadIdx.x;
    float4 v = pred[i];
    bool neg = (v.x < 0.f) | (v.y < 0.f) | (v.z < 0.f) | (v.w < 0.f);
    bool bneg = __syncthreads_or(neg);
    __shared__ bool last;
    if (threadIdx.x == 0) {
        if (bneg) atomicOr(&g_neg, 1);
        __threadfence();
        last = (atomicAdd(&g_ctrf, 1) == (int)gridDim.x - 1);
    }
    __syncthreads();
    if (last && threadIdx.x == 0) { g_flag = g_neg; g_neg = 0; g_ctrf = 0; }
}

// Per 32x32 tile: masks, in-tile CCL in smem, labels out as global-index tile
// roots. g_mm initialized ONLY at pred tile-root pixels.
__global__ void k_tile(const float* __restrict__ pred,
                       const float* __restrict__ target) {
    __shared__ int lp[TS * TS];
    __shared__ int lt[TS * TS];
    int lx = threadIdx.x, ly = threadIdx.y;
    int l  = ly * TS + lx;
    int gx = blockIdx.x * TS + lx;
    int gy = blockIdx.y * TS + ly;
    int b  = blockIdx.z;
    int gi = b * HWSZ + gy * WW + gx;

    bool  resc = (g_flag != 0);
    float p = pred[gi];
    float t = target[gi];
    float pp  = resc ? resc01(p) : p;
    float t01 = resc01(t);
    bool mp = pp  > 0.5f;
    bool mt = t01 > 0.5f;

    lp[l] = mp ? l : -1;
    lt[l] = mt ? l : -1;
    __syncthreads();

    if (mp) {
        if (lx > 0 && lp[l - 1]  >= 0) s_union(lp, l, l - 1);
        if (ly > 0 && lp[l - TS] >= 0) s_union(lp, l, l - TS);
    }
    if (mt) {
        if (lx > 0 && lt[l - 1]  >= 0) s_union(lt, l, l - 1);
        if (ly > 0 && lt[l - TS] >= 0) s_union(lt, l, l - TS);
    }
    __syncthreads();

    int rp = -1, rt = -1;
    if (mp) {
        int r = s_find(lp, l);
        if (r == l) g_mm[gi] = make_int2(INT_MAX, -1);   // root-only init
        rp = b * HWSZ + (blockIdx.y * TS + (r >> 5)) * WW + blockIdx.x * TS + (r & 31);
    }
    if (mt) {
        int r = s_find(lt, l);
        rt = b * HWSZ + (blockIdx.y * TS + (r >> 5)) * WW + blockIdx.x * TS + (r & 31);
    }
    g_labp[gi] = rp;
    g_labt[gi] = rt;
}

// Merge across tile boundaries (both masks; one thread = one edge, one mask).
__global__ void k_bmerge() {
    int tid = blockIdx.x * blockDim.x + threadIdx.x;
    if (tid >= NEDGE) return;
    int m = tid / (BB * EPI);
    int r = tid % (BB * EPI);
    int b = r / EPI;
    int e = r % EPI;
    int* L = m ? g_labt : g_labp;

    int idx, n;
    if (e < EPT) {                       // vertical boundary: (y,x)-(y,x-1)
        int bi = e / HH, y = e % HH;
        int x  = TS * (bi + 1);
        idx = b * HWSZ + y * WW + x;
        n   = idx - 1;
    } else {                             // horizontal boundary: (y,x)-(y-1,x)
        e -= EPT;
        int bi = e / WW, x = e % WW;
        int y  = TS * (bi + 1);
        idx = b * HWSZ + y * WW + x;
        n   = idx - WW;
    }
    if (L[idx] >= 0 && L[n] >= 0) uf_union(L, idx, n);
}

// Flatten pred labels to final roots + per-pred-root target min/max.
// Warp-deduplicated chases and warp-grouped atomics.
__global__ void k_flat_agg() {
    int i = blockIdx.x * blockDim.x + threadIdx.x;   // exact cover of NTOT
    int lane = threadIdx.x & 31;
    int lpv = g_labp[i];
    int ltv = g_labt[i];

    int rp = warp_findc(g_labp, lpv);
    int rt = warp_findc(g_labt, ltv);
    g_labp[i] = rp;

    bool pair = (rp >= 0) && (rt >= 0);
    unsigned valid = __ballot_sync(0xffffffffu, pair);
    if (pair) {
        unsigned grp = __match_any_sync(valid, rp);  // lanes sharing pred root
        int mn = rt, mx = rt;
        unsigned rest = grp & ~(1u << lane);
        while (rest) {
            int src = __ffs(rest) - 1;
            rest &= rest - 1;
            int o = __shfl_sync(grp, rt, src);
            mn = min(mn, o);
            mx = max(mx, o);
        }
        if (lane == __ffs(grp) - 1) {
            atomicMin(&g_mm[rp].x, mn);
            atomicMax(&g_mm[rp].y, mx);
        }
    }
}

// Weighted loss + fused deterministic final reduction (last-block pattern).
__global__ void k_loss(const float4* __restrict__ pred,
                       const float4* __restrict__ target,
                       float* __restrict__ out) {
    __shared__ double sh[256];
    bool resc = (g_flag != 0);
    int v = blockIdx.x * blockDim.x + threadIdx.x;   // exact cover of N4
    float4 p = pred[v];
    float4 t = target[v];
    int4   a = ((const int4*)g_labp)[v];
    float pv[4] = {p.x, p.y, p.z, p.w};
    float tv[4] = {t.x, t.y, t.z, t.w};
    int   av[4] = {a.x, a.y, a.z, a.w};

    double s = 0.0;
    #pragma unroll
    for (int j = 0; j < 4; j++) {
        float pp  = resc ? resc01(pv[j]) : pv[j];
        float t01 = resc01(tv[j]);
        float pl  = fabsf(pp - t01);
        float w   = 1.0f;
        if (av[j] >= 0 && !(t01 > 0.5f)) {     // pred fg, target bg
            int2 mm = g_mm[av[j]];
            if (mm.y > mm.x) w = 11.0f;        // merged component
        }
        s += (double)(pl * w);
    }

    sh[threadIdx.x] = s;
    __syncthreads();
    for (int off = 128; off > 0; off >>= 1) {
        if (threadIdx.x < off) sh[threadIdx.x] += sh[threadIdx.x + off];
        __syncthreads();
    }
    __shared__ bool last;
    if (threadIdx.x == 0) {
        g_psum[blockIdx.x] = sh[0];
        __threadfence();
        last = (atomicAdd(&g_ctr, 1) == (int)gridDim.x - 1);
    }
    __syncthreads();

    if (last) {
        double s2 = 0.0;
        for (int k = 0; k < LOSS_BLOCKS / 256; k++)          // fixed order
            s2 += g_psum[threadIdx.x + 256 * k];
        sh[threadIdx.x] = s2;
        __syncthreads();
        for (int off = 128; off > 0; off >>= 1) {
            if (threadIdx.x < off) sh[threadIdx.x] += sh[threadIdx.x + off];
            __syncthreads();
        }
        if (threadIdx.x == 0) {
            out[0] = (float)(sh[0] / (double)NTOT);
            g_ctr = 0;                                       // reset for replay
        }
    }
}

// ---------------------------------------------------------------------------
extern "C" void kernel_launch(void* const* d_in, const int* in_sizes, int n_in,
                              void* d_out, int out_size) {
    const float* pred   = (const float*)d_in[0];
    const float* target = (const float*)d_in[1];
    float* out = (float*)d_out;

    k_flag<<<N4 / 256, 256>>>((const float4*)pred);
    k_tile<<<dim3(TILES_X, TILES_Y, BB), dim3(TS, TS)>>>(pred, target);
    k_bmerge<<<(NEDGE + 255) / 256, 256>>>();
    k_flat_agg<<<NTOT / 256, 256>>>();
    k_loss<<<LOSS_BLOCKS, 256>>>((const float4*)pred, (const float4*)target, out);
}